// round 14
// baseline (speedup 1.0000x reference)
#include <cuda_runtime.h>
#include <cstdint>

// Input:  x (2,8,256,256) fp32, F (3,3) fp32
// Output: (2,8,256,256) fp32 epipolar line-sum.
//
// Pipeline:
//  1) transpose_k : x -> g_t4[h][w][pg] (4-plane float4 chunks)
//  2) work_k      : blocks 0..255 = col+row P prefix tables
//                   blocks 256..  = warp/pixel exact index + telescoped records
//                   (|step| <= 1 guaranteed -> exactly ONE record per boundary)
//  3) qderive_k   : Q[c][t] = P[c][t] - P[c-1][t]  (pointwise, no scan)
//  4) gather_k    : ONE table load per record
//     record = ci | t<<8 | neg<<17 | isQ<<18
//     out = -P[c_first][T0] + sum(+/-Q[c][t] at steps) + P[c_last][T1]

#define FULLM 0xffffffffu
#define S_TAB (256 * 257)
#define RCAP  272                                  // records/pixel capacity

__device__ float4   g_t4 [256 * 256 * 4];          // 4 MB repacked image
__device__ unsigned g_run[256 * 256 * RCAP];       // record stream
__device__ int      g_nrun[256 * 256];
__device__ float4   g_tab[4 * S_TAB * 4];          // [colP][colQ][rowP][rowQ]

__global__ void __launch_bounds__(256) transpose_k(const float* __restrict__ in) {
    int gid = blockIdx.x * 256 + threadIdx.x;
    int px = gid >> 2, pg = gid & 3;
    float4 o;
    o.x = __ldg(in + (pg * 4 + 0) * 65536 + px);
    o.y = __ldg(in + (pg * 4 + 1) * 65536 + px);
    o.z = __ldg(in + (pg * 4 + 2) * 65536 + px);
    o.w = __ldg(in + (pg * 4 + 3) * 65536 + px);
    g_t4[px * 4 + pg] = o;
}

// Warp-serial exclusive prefix of one (line, pg). is_col -> region 0, else region 2.
__device__ __forceinline__ void prefix_line(int line, int pg, bool is_col, int lane) {
    float4* __restrict__ Pt = g_tab + ((is_col ? 0 : 2) * S_TAB + line * 257) * 4;
    float4 carry = make_float4(0.f, 0.f, 0.f, 0.f);
    if (lane == 0) Pt[pg] = carry;
#pragma unroll
    for (int r = 0; r < 8; ++r) {
        int t = r * 32 + lane;
        int px = is_col ? (line * 256 + t) : (t * 256 + line);
        float4 s = __ldg(g_t4 + px * 4 + pg);
#pragma unroll
        for (int d = 1; d < 32; d <<= 1) {
            float ax = __shfl_up_sync(FULLM, s.x, d);
            float ay = __shfl_up_sync(FULLM, s.y, d);
            float az = __shfl_up_sync(FULLM, s.z, d);
            float aw = __shfl_up_sync(FULLM, s.w, d);
            if (lane >= d) { s.x += ax; s.y += ay; s.z += az; s.w += aw; }
        }
        Pt[(t + 1) * 4 + pg] =
            make_float4(carry.x + s.x, carry.y + s.y, carry.z + s.z, carry.w + s.w);
        carry.x += __shfl_sync(FULLM, s.x, 31);
        carry.y += __shfl_sync(FULLM, s.y, 31);
        carry.z += __shfl_sync(FULLM, s.z, 31);
        carry.w += __shfl_sync(FULLM, s.w, 31);
    }
}

// Q tables pointwise from P: Q[c][t] = P[c][t] - P[c-1][t]; Q[0][*] = 0.
__global__ void __launch_bounds__(256) qderive_k() {
    int gid = blockIdx.x * 256 + threadIdx.x;       // < 2*256*257*4 = 526336
    if (gid >= 2 * S_TAB * 4) return;
    int pg  = gid & 3;
    int rem = gid >> 2;
    int reg = rem / S_TAB;                          // 0 = col, 1 = row
    int ct  = rem - reg * S_TAB;
    int c   = ct / 257;
    const float4* __restrict__ Pt = g_tab + (reg * 2 * S_TAB) * 4;
    float4* __restrict__ Qt = g_tab + ((reg * 2 + 1) * S_TAB) * 4;
    float4 o = make_float4(0.f, 0.f, 0.f, 0.f);
    if (c > 0) {
        float4 a = __ldg(Pt + ct * 4 + pg);
        float4 b = __ldg(Pt + (ct - 257) * 4 + pg);
        o = make_float4(a.x - b.x, a.y - b.y, a.z - b.z, a.w - b.w);
    }
    Qt[ct * 4 + pg] = o;
}

// Warp per pixel: EXACT index arithmetic (R4..R13 — do not touch) +
// branch-light telescoped record emission (one record per boundary).
__device__ __forceinline__ void idx_rle_pixel(const float* __restrict__ Fm,
                                              int px, int lane) {
    const int w = px & 255, h = px >> 8;
    const float u = (float)w, v = (float)h;

    const float F0 = __ldg(Fm+0), F1 = __ldg(Fm+1), F2 = __ldg(Fm+2);
    const float F3 = __ldg(Fm+3), F4 = __ldg(Fm+4), F5 = __ldg(Fm+5);
    const float F6 = __ldg(Fm+6), F7 = __ldg(Fm+7), F8 = __ldg(Fm+8);
    float A = __fadd_rn(__fmaf_rn(F3, v, __fmul_rn(F0, u)), F6);
    float B = __fadd_rn(__fmaf_rn(F4, v, __fmul_rn(F1, u)), F7);
    float C = __fadd_rn(__fmaf_rn(F5, v, __fmul_rn(F2, u)), F8);

    const bool col = (fabsf(B) >= fabsf(A));
    float P, Q;
    if (col) { P = A; Q = (fabsf(B) < 1e-8f) ? 1e-8f : B; }
    else     { P = B; Q = (fabsf(A) < 1e-8f) ? 1e-8f : A; }
    const float rq  = __frcp_rn(Q);
    const float nrq = -rq;

    unsigned vals[8];
    float tf = (float)(lane * 8);
#pragma unroll
    for (int j = 0; j < 8; ++j, tf += 1.0f) {
        float n  = __fmaf_rn(P, tf, C);
        float yf = __fmul_rn(n, nrq);
        int   ci = __float2int_rn(yf);
        float d  = yf - (float)ci;
        if (0.5f - fabsf(d) < 5e-4f) {
            ci = __float2int_rn(__fdiv_rn(-n, Q));
        }
        vals[j] = ((unsigned)ci < 256u) ? (unsigned)ci : 0xFFFFu;
    }

    unsigned prev = __shfl_up_sync(FULLM, vals[7], 1);
    if (lane == 0) prev = 0xFFFFu;                  // before t=0: invalid

    // Boundary mask: every change (incl. valid<->invalid) = exactly 1 record.
    unsigned m = 0;
    {
        unsigned p = prev;
#pragma unroll
        for (int k = 0; k < 8; ++k) {
            if (vals[k] != p) m |= 1u << k;
            p = vals[k];
        }
    }
    unsigned cnt = __popc(m);
    if (lane == 31 && vals[7] != 0xFFFFu) cnt += 1; // tail record at t=256

    unsigned off = cnt;
#pragma unroll
    for (int d = 1; d < 32; d <<= 1) {
        unsigned o = __shfl_up_sync(FULLM, off, d);
        if (lane >= d) off += o;
    }
    unsigned total = __shfl_sync(FULLM, off, 31);
    off -= cnt;
    if (lane == 31) g_nrun[px] = (int)total;

    unsigned cur = (unsigned)px * RCAP + off;
    {
        unsigned p = prev;
#pragma unroll
        for (int k = 0; k < 8; ++k) {
            unsigned b = vals[k];
            if (b != p) {
                unsigned t = (unsigned)(lane * 8 + k);
                unsigned rec;
                if (p == 0xFFFFu)      rec = b | (t << 8) | (1u << 17);              // start: -P[b][t]
                else if (b == 0xFFFFu) rec = p | (t << 8);                           // end:   +P[p][t]
                else if (b > p)        rec = b | (t << 8) | (1u << 17) | (1u << 18); // up:   -Q[b][t]
                else                   rec = p | (t << 8) | (1u << 18);              // down: +Q[p][t]
                g_run[cur++] = rec;
            }
            p = b;
        }
    }
    if (lane == 31 && vals[7] != 0xFFFFu)           // +P[c_last][256]
        g_run[cur] = vals[7] | (256u << 8);
}

// blocks 0..255: 2048 P-prefix warps; blocks 256..8447: warp-per-pixel records
__global__ void __launch_bounds__(256) work_k(const float* __restrict__ Fm) {
    const int lane = threadIdx.x & 31;
    const int warp = threadIdx.x >> 5;
    if (blockIdx.x < 256) {
        int wg = blockIdx.x * 8 + warp;             // 0..2047
        prefix_line((wg >> 2) & 255, wg & 3, wg < 1024, lane);
    } else {
        int px = (blockIdx.x - 256) * 8 + warp;
        idx_rle_pixel(Fm, px, lane);
    }
}

// Block = 8x8 pixel tile. Warp = 8 pixels x 4 pg. ONE table load per record.
__global__ void __launch_bounds__(256) gather_k(const float* __restrict__ Fm,
                                                float* __restrict__ out) {
    const int lane = threadIdx.x & 31;
    const int warp = threadIdx.x >> 5;
    const int pg   = lane & 3;
    const int pix  = lane >> 2;
    const int h = blockIdx.x * 8 + warp;
    const int w = blockIdx.y * 8 + pix;
    const int px = h * 256 + w;
    const float u = (float)w, v = (float)h;

    // mode bit — exact same computation as idx_rle_pixel
    const float F0 = __ldg(Fm+0), F1 = __ldg(Fm+1);
    const float F3 = __ldg(Fm+3), F4 = __ldg(Fm+4);
    const float F6 = __ldg(Fm+6), F7 = __ldg(Fm+7);
    float A = __fadd_rn(__fmaf_rn(F3, v, __fmul_rn(F0, u)), F6);
    float B = __fadd_rn(__fmaf_rn(F4, v, __fmul_rn(F1, u)), F7);
    const bool col = (fabsf(B) >= fabsf(A));
    const float4* __restrict__ Tb = g_tab + (col ? 0 : 2 * S_TAB) * 4 + pg;

    int n = __ldg(g_nrun + px);
    int nmax = n;
#pragma unroll
    for (int d = 16; d; d >>= 1)
        nmax = max(nmax, __shfl_xor_sync(FULLM, nmax, d));

    const uint4* __restrict__ rv =
        reinterpret_cast<const uint4*>(g_run + (size_t)px * RCAP);

    float4 acc0 = make_float4(0.f, 0.f, 0.f, 0.f);
    float4 acc1 = make_float4(0.f, 0.f, 0.f, 0.f);
    uint4 V = make_uint4(0u, 0u, 0u, 0u);
    for (int j = 0; j < nmax; ++j) {
        if ((j & 3) == 0) V = __ldg(rv + (j >> 2));
        unsigned word = (j & 3) == 0 ? V.x : (j & 3) == 1 ? V.y
                       : (j & 3) == 2 ? V.z : V.w;
        if (j < n) {
            int   c  = word & 255;
            int   t  = (word >> 8) & 511;
            float s  = (word & (1u << 17)) ? -1.0f : 1.0f;
            int   kq = (word >> 18) & 1;
            float4 val = __ldg(Tb + (kq * S_TAB + c * 257 + t) * 4);
            if (j & 1) {
                acc1.x = __fmaf_rn(s, val.x, acc1.x);
                acc1.y = __fmaf_rn(s, val.y, acc1.y);
                acc1.z = __fmaf_rn(s, val.z, acc1.z);
                acc1.w = __fmaf_rn(s, val.w, acc1.w);
            } else {
                acc0.x = __fmaf_rn(s, val.x, acc0.x);
                acc0.y = __fmaf_rn(s, val.y, acc0.y);
                acc0.z = __fmaf_rn(s, val.z, acc0.z);
                acc0.w = __fmaf_rn(s, val.w, acc0.w);
            }
        }
    }
    float4 acc = make_float4(acc0.x + acc1.x, acc0.y + acc1.y,
                             acc0.z + acc1.z, acc0.w + acc1.w);

    out[(pg * 4 + 0) * 65536 + px] = acc.x;
    out[(pg * 4 + 1) * 65536 + px] = acc.y;
    out[(pg * 4 + 2) * 65536 + px] = acc.z;
    out[(pg * 4 + 3) * 65536 + px] = acc.w;
}

extern "C" void kernel_launch(void* const* d_in, const int* in_sizes, int n_in,
                              void* d_out, int out_size) {
    const float* img = (const float*)d_in[0];
    const float* F   = (const float*)d_in[1];
    if (n_in >= 2 && in_sizes[0] == 9) {            // defensive: input order swap
        img = (const float*)d_in[1];
        F   = (const float*)d_in[0];
    }
    float* out = (float*)d_out;

    transpose_k<<<1024, 256>>>(img);
    work_k<<<8448, 256>>>(F);
    qderive_k<<<2056, 256>>>();
    dim3 ggat(32, 32);
    gather_k<<<ggat, 256>>>(F, out);
}

// round 15
// speedup vs baseline: 1.4276x; 1.4276x over previous
#include <cuda_runtime.h>
#include <cstdint>

// Input:  x (2,8,256,256) fp32, F (3,3) fp32
// Output: (2,8,256,256) fp32 epipolar line-sum.
//
// Pipeline (R12 structure; gather runs split across 2 lanes per pixel):
//  1) transpose_k : x -> g_t4[h][w][pg] (4-plane float4 chunks)
//  2) work_k      : blocks 0..255  = col+row exclusive prefix tables
//                   blocks 256..   = warp-per-pixel exact index + in-register RLE
//  3) gather_k    : per run: acc += P[ci][t1] - P[ci][t0]; runs split even/odd
//                   across lane pairs (2x MLP, half the serial trips)

#define FULLM 0xffffffffu

__device__ float4   g_t4 [256 * 256 * 4];        // 4 MB   repacked image
__device__ unsigned g_run[256 * 256 * 264];      // 69 MB  packed runs: ci|t0<<9|t1<<18
__device__ int      g_nrun[256 * 256];
__device__ float4   g_pc [256 * 257 * 4];        // 4.2MB  col prefix: line=h, t=w
__device__ float4   g_pr [256 * 257 * 4];        // 4.2MB  row prefix: line=w, t=h

__global__ void __launch_bounds__(256) transpose_k(const float* __restrict__ in) {
    int gid = blockIdx.x * 256 + threadIdx.x;    // 262144 = 65536 px * 4 groups
    int px = gid >> 2, pg = gid & 3;
    float4 o;
    o.x = __ldg(in + (pg * 4 + 0) * 65536 + px);
    o.y = __ldg(in + (pg * 4 + 1) * 65536 + px);
    o.z = __ldg(in + (pg * 4 + 2) * 65536 + px);
    o.w = __ldg(in + (pg * 4 + 3) * 65536 + px);
    g_t4[px * 4 + pg] = o;
}

// Warp-serial exclusive prefix of one (line, pg) in direction dir.
__device__ __forceinline__ void prefix_line(int line, int pg, bool is_col, int lane) {
    float4* __restrict__ Pt = is_col ? g_pc : g_pr;
    float4 carry = make_float4(0.f, 0.f, 0.f, 0.f);
    if (lane == 0) Pt[(line * 257) * 4 + pg] = carry;
#pragma unroll
    for (int r = 0; r < 8; ++r) {
        int t = r * 32 + lane;
        int px = is_col ? (line * 256 + t) : (t * 256 + line);
        float4 s = __ldg(g_t4 + px * 4 + pg);
#pragma unroll
        for (int d = 1; d < 32; d <<= 1) {
            float ax = __shfl_up_sync(FULLM, s.x, d);
            float ay = __shfl_up_sync(FULLM, s.y, d);
            float az = __shfl_up_sync(FULLM, s.z, d);
            float aw = __shfl_up_sync(FULLM, s.w, d);
            if (lane >= d) { s.x += ax; s.y += ay; s.z += az; s.w += aw; }
        }
        Pt[(line * 257 + t + 1) * 4 + pg] =
            make_float4(carry.x + s.x, carry.y + s.y, carry.z + s.z, carry.w + s.w);
        carry.x += __shfl_sync(FULLM, s.x, 31);
        carry.y += __shfl_sync(FULLM, s.y, 31);
        carry.z += __shfl_sync(FULLM, s.z, 31);
        carry.w += __shfl_sync(FULLM, s.w, 31);
    }
}

// Warp per pixel: EXACT index arithmetic (R4..R12 — do not touch) + in-register RLE.
__device__ __forceinline__ void idx_rle_pixel(const float* __restrict__ Fm,
                                              int px, int lane) {
    const int w = px & 255, h = px >> 8;
    const float u = (float)w, v = (float)h;

    const float F0 = __ldg(Fm+0), F1 = __ldg(Fm+1), F2 = __ldg(Fm+2);
    const float F3 = __ldg(Fm+3), F4 = __ldg(Fm+4), F5 = __ldg(Fm+5);
    const float F6 = __ldg(Fm+6), F7 = __ldg(Fm+7), F8 = __ldg(Fm+8);
    float A = __fadd_rn(__fmaf_rn(F3, v, __fmul_rn(F0, u)), F6);
    float B = __fadd_rn(__fmaf_rn(F4, v, __fmul_rn(F1, u)), F7);
    float C = __fadd_rn(__fmaf_rn(F5, v, __fmul_rn(F2, u)), F8);

    const bool col = (fabsf(B) >= fabsf(A));
    float P, Q;
    if (col) { P = A; Q = (fabsf(B) < 1e-8f) ? 1e-8f : B; }
    else     { P = B; Q = (fabsf(A) < 1e-8f) ? 1e-8f : A; }
    const float rq  = __frcp_rn(Q);
    const float nrq = -rq;

    unsigned vals[8];
    float tf = (float)(lane * 8);
#pragma unroll
    for (int j = 0; j < 8; ++j, tf += 1.0f) {
        float n  = __fmaf_rn(P, tf, C);
        float yf = __fmul_rn(n, nrq);
        int   ci = __float2int_rn(yf);
        float d  = yf - (float)ci;
        if (0.5f - fabsf(d) < 5e-4f) {
            ci = __float2int_rn(__fdiv_rn(-n, Q));
        }
        vals[j] = ((unsigned)ci < 256u) ? (unsigned)ci : 0xFFFFu;
    }

    unsigned prev = __shfl_up_sync(FULLM, vals[7], 1);
    if (lane == 0) prev = 0x10000u;                 // t=0 always a run start

    unsigned m = 0, vm = 0;
#pragma unroll
    for (int k = 0; k < 8; ++k) {
        if (vals[k] != prev)      m  |= 1u << k;
        if (vals[k] != 0xFFFFu)   vm |= 1u << k;
        prev = vals[k];
    }

    unsigned cnt = __popc(m & vm);
    unsigned off = cnt;
#pragma unroll
    for (int d = 1; d < 32; d <<= 1) {
        unsigned o = __shfl_up_sync(FULLM, off, d);
        if (lane >= d) off += o;
    }
    unsigned total = __shfl_sync(FULLM, off, 31);
    off -= cnt;
    if (lane == 31) g_nrun[px] = (int)total;

    unsigned Bb = __ballot_sync(FULLM, m != 0);
    unsigned hmask = (lane == 31) ? 0u : (FULLM << (lane + 1));
    unsigned nb = Bb & hmask;
    int nl = nb ? (__ffs(nb) - 1) : lane;
    unsigned m2 = __shfl_sync(FULLM, m, nl);
    int cross_t1 = nb ? (nl * 8 + __ffs(m2) - 1) : 256;

    unsigned base = (unsigned)px * 264u + off;
#pragma unroll
    for (int k = 0; k < 8; ++k) {
        if (((m >> k) & 1u) && ((vm >> k) & 1u)) {
            unsigned rem = m >> (k + 1);
            int t1 = rem ? (lane * 8 + k + 1 + __ffs(rem) - 1) : cross_t1;
            int t0 = lane * 8 + k;
            g_run[base++] = vals[k] | ((unsigned)t0 << 9) | ((unsigned)t1 << 18);
        }
    }
}

// blocks 0..255: 2048 prefix warps (dir x 256 lines x 4 pg)
// blocks 256..8447: warp-per-pixel index+RLE (65536 pixels)
__global__ void __launch_bounds__(256) work_k(const float* __restrict__ Fm) {
    const int lane = threadIdx.x & 31;
    const int warp = threadIdx.x >> 5;
    if (blockIdx.x < 256) {
        int wg = blockIdx.x * 8 + warp;             // 0..2047
        prefix_line((wg >> 2) & 255, wg & 3, wg < 1024, lane);
    } else {
        int px = (blockIdx.x - 256) * 8 + warp;     // 0..65535
        idx_rle_pixel(Fm, px, lane);
    }
}

// Warp = 4 pixels x 4 pg x 2 run-parity lanes. Block = 8x4 pixel tile.
// Each lane handles runs j == rp (mod 2): half the serial trips, 2x MLP.
__global__ void __launch_bounds__(256) gather_k(const float* __restrict__ Fm,
                                                float* __restrict__ out) {
    const int lane = threadIdx.x & 31;
    const int warp = threadIdx.x >> 5;
    const int pg   = lane & 3;
    const int rp   = (lane >> 2) & 1;               // run parity for this lane
    const int pix  = lane >> 3;                     // 0..3
    const int h = blockIdx.x * 8 + warp;
    const int w = blockIdx.y * 4 + pix;
    const int px = h * 256 + w;
    const float u = (float)w, v = (float)h;

    // mode bit — exact same computation as idx_rle_pixel
    const float F0 = __ldg(Fm+0), F1 = __ldg(Fm+1);
    const float F3 = __ldg(Fm+3), F4 = __ldg(Fm+4);
    const float F6 = __ldg(Fm+6), F7 = __ldg(Fm+7);
    float A = __fadd_rn(__fmaf_rn(F3, v, __fmul_rn(F0, u)), F6);
    float B = __fadd_rn(__fmaf_rn(F4, v, __fmul_rn(F1, u)), F7);
    const bool col = (fabsf(B) >= fabsf(A));
    const float4* __restrict__ Ptab = col ? g_pc : g_pr;

    int n = __ldg(g_nrun + px);
    int nmax = n;
#pragma unroll
    for (int d = 16; d; d >>= 1)
        nmax = max(nmax, __shfl_xor_sync(FULLM, nmax, d));
    int trips = (nmax + 1) >> 1;

    const uint4* __restrict__ rv =
        reinterpret_cast<const uint4*>(g_run + (size_t)px * 264u);

    float4 acc = make_float4(0.f, 0.f, 0.f, 0.f);
    uint4 V = make_uint4(0u, 0u, 0u, 0u);
    for (int k = 0; k < trips; ++k) {
        if ((k & 1) == 0) V = __ldg(rv + (k >> 1));
        int j = 2 * k + rp;
        unsigned word = (k & 1) ? (rp ? V.w : V.z) : (rp ? V.y : V.x);
        if (j < n) {
            int ci = word & 511;
            int t0 = (word >> 9) & 511;
            int t1 = word >> 18;
            float4 lo = __ldg(Ptab + (ci * 257 + t0) * 4 + pg);
            float4 hi = __ldg(Ptab + (ci * 257 + t1) * 4 + pg);
            acc.x += hi.x - lo.x;
            acc.y += hi.y - lo.y;
            acc.z += hi.z - lo.z;
            acc.w += hi.w - lo.w;
        }
    }

    // Combine run parities (lane ^ 4 = partner with same pg, pix).
    acc.x += __shfl_xor_sync(FULLM, acc.x, 4);
    acc.y += __shfl_xor_sync(FULLM, acc.y, 4);
    acc.z += __shfl_xor_sync(FULLM, acc.z, 4);
    acc.w += __shfl_xor_sync(FULLM, acc.w, 4);

    // Both parity lanes hold the full 4-plane sum; split the stores.
    const int p0 = pg * 4 + rp * 2;
    float v0 = rp ? acc.z : acc.x;
    float v1 = rp ? acc.w : acc.y;
    out[(p0    ) * 65536 + px] = v0;
    out[(p0 + 1) * 65536 + px] = v1;
}

extern "C" void kernel_launch(void* const* d_in, const int* in_sizes, int n_in,
                              void* d_out, int out_size) {
    const float* img = (const float*)d_in[0];
    const float* F   = (const float*)d_in[1];
    if (n_in >= 2 && in_sizes[0] == 9) {            // defensive: input order swap
        img = (const float*)d_in[1];
        F   = (const float*)d_in[0];
    }
    float* out = (float*)d_out;

    transpose_k<<<1024, 256>>>(img);
    work_k<<<8448, 256>>>(F);
    dim3 ggat(32, 64);
    gather_k<<<ggat, 256>>>(F, out);
}

// round 16
// speedup vs baseline: 1.4935x; 1.0461x over previous
#include <cuda_runtime.h>
#include <cstdint>

// Input:  x (2,8,256,256) fp32, F (3,3) fp32
// Output: (2,8,256,256) fp32 epipolar line-sum.
//
// Pipeline:
//  1) transpose_k : x -> g_t4[h][w][pg] (4-plane float4 chunks)
//  2) prefix_k    : col+row exclusive prefix tables P
//  3) fused_k     : per block = 8 pixels; phase1 warp/pixel exact idx + RLE -> smem;
//                   phase2 warp/pixel gather (4 pg x 8 run-stride lanes)

#define FULLM 0xffffffffu
#define RCAP  264

__device__ float4 g_t4[256 * 256 * 4];           // 4 MB   repacked image
__device__ float4 g_pc [256 * 257 * 4];          // 4.2MB  col prefix: line=h, t=w
__device__ float4 g_pr [256 * 257 * 4];          // 4.2MB  row prefix: line=w, t=h

__global__ void __launch_bounds__(256) transpose_k(const float* __restrict__ in) {
    int gid = blockIdx.x * 256 + threadIdx.x;    // 262144 = 65536 px * 4 groups
    int px = gid >> 2, pg = gid & 3;
    float4 o;
    o.x = __ldg(in + (pg * 4 + 0) * 65536 + px);
    o.y = __ldg(in + (pg * 4 + 1) * 65536 + px);
    o.z = __ldg(in + (pg * 4 + 2) * 65536 + px);
    o.w = __ldg(in + (pg * 4 + 3) * 65536 + px);
    g_t4[px * 4 + pg] = o;
}

// Warp-serial exclusive prefix of one (line, pg) in direction dir.
__global__ void __launch_bounds__(256) prefix_k() {
    const int lane = threadIdx.x & 31;
    const int wg   = blockIdx.x * 8 + (threadIdx.x >> 5);  // 0..2047
    const int line = (wg >> 2) & 255;
    const int pg   = wg & 3;
    const bool is_col = wg < 1024;
    float4* __restrict__ Pt = is_col ? g_pc : g_pr;
    float4 carry = make_float4(0.f, 0.f, 0.f, 0.f);
    if (lane == 0) Pt[(line * 257) * 4 + pg] = carry;
#pragma unroll
    for (int r = 0; r < 8; ++r) {
        int t = r * 32 + lane;
        int px = is_col ? (line * 256 + t) : (t * 256 + line);
        float4 s = __ldg(g_t4 + px * 4 + pg);
#pragma unroll
        for (int d = 1; d < 32; d <<= 1) {
            float ax = __shfl_up_sync(FULLM, s.x, d);
            float ay = __shfl_up_sync(FULLM, s.y, d);
            float az = __shfl_up_sync(FULLM, s.z, d);
            float aw = __shfl_up_sync(FULLM, s.w, d);
            if (lane >= d) { s.x += ax; s.y += ay; s.z += az; s.w += aw; }
        }
        Pt[(line * 257 + t + 1) * 4 + pg] =
            make_float4(carry.x + s.x, carry.y + s.y, carry.z + s.z, carry.w + s.w);
        carry.x += __shfl_sync(FULLM, s.x, 31);
        carry.y += __shfl_sync(FULLM, s.y, 31);
        carry.z += __shfl_sync(FULLM, s.z, 31);
        carry.w += __shfl_sync(FULLM, s.w, 31);
    }
}

// Block = 8 consecutive-w pixels. Phase1: warp/pixel idx+RLE to smem.
// Phase2: warp/pixel gather, lanes = pg(0..3) x runstride(0..7).
__global__ void __launch_bounds__(256) fused_k(const float* __restrict__ Fm,
                                               float* __restrict__ out) {
    __shared__ unsigned s_run[8][RCAP];
    __shared__ int      s_n[8];
    __shared__ unsigned s_mode[8];                  // 1 = col

    const int lane = threadIdx.x & 31;
    const int warp = threadIdx.x >> 5;
    const int h     = blockIdx.x >> 5;
    const int wbase = (blockIdx.x & 31) * 8;
    const int w  = wbase + warp;
    const int px = h * 256 + w;
    const float u = (float)w, v = (float)h;

    // ---- Phase 1: EXACT index arithmetic (R4..R12 — do not touch) + RLE ----
    const float F0 = __ldg(Fm+0), F1 = __ldg(Fm+1), F2 = __ldg(Fm+2);
    const float F3 = __ldg(Fm+3), F4 = __ldg(Fm+4), F5 = __ldg(Fm+5);
    const float F6 = __ldg(Fm+6), F7 = __ldg(Fm+7), F8 = __ldg(Fm+8);
    float A = __fadd_rn(__fmaf_rn(F3, v, __fmul_rn(F0, u)), F6);
    float B = __fadd_rn(__fmaf_rn(F4, v, __fmul_rn(F1, u)), F7);
    float C = __fadd_rn(__fmaf_rn(F5, v, __fmul_rn(F2, u)), F8);

    const bool col = (fabsf(B) >= fabsf(A));
    float P, Q;
    if (col) { P = A; Q = (fabsf(B) < 1e-8f) ? 1e-8f : B; }
    else     { P = B; Q = (fabsf(A) < 1e-8f) ? 1e-8f : A; }
    const float rq  = __frcp_rn(Q);
    const float nrq = -rq;

    unsigned vals[8];
    float tf = (float)(lane * 8);
#pragma unroll
    for (int j = 0; j < 8; ++j, tf += 1.0f) {
        float n  = __fmaf_rn(P, tf, C);
        float yf = __fmul_rn(n, nrq);
        int   ci = __float2int_rn(yf);
        float d  = yf - (float)ci;
        if (0.5f - fabsf(d) < 5e-4f) {
            ci = __float2int_rn(__fdiv_rn(-n, Q));
        }
        vals[j] = ((unsigned)ci < 256u) ? (unsigned)ci : 0xFFFFu;
    }

    unsigned prev = __shfl_up_sync(FULLM, vals[7], 1);
    if (lane == 0) prev = 0x10000u;                 // t=0 always a run start

    unsigned m = 0, vm = 0;
#pragma unroll
    for (int k = 0; k < 8; ++k) {
        if (vals[k] != prev)      m  |= 1u << k;
        if (vals[k] != 0xFFFFu)   vm |= 1u << k;
        prev = vals[k];
    }

    unsigned cnt = __popc(m & vm);
    unsigned off = cnt;
#pragma unroll
    for (int d = 1; d < 32; d <<= 1) {
        unsigned o = __shfl_up_sync(FULLM, off, d);
        if (lane >= d) off += o;
    }
    unsigned total = __shfl_sync(FULLM, off, 31);
    off -= cnt;
    if (lane == 31) { s_n[warp] = (int)total; s_mode[warp] = col ? 1u : 0u; }

    unsigned Bb = __ballot_sync(FULLM, m != 0);
    unsigned hmask = (lane == 31) ? 0u : (FULLM << (lane + 1));
    unsigned nb = Bb & hmask;
    int nl = nb ? (__ffs(nb) - 1) : lane;
    unsigned m2 = __shfl_sync(FULLM, m, nl);
    int cross_t1 = nb ? (nl * 8 + __ffs(m2) - 1) : 256;

    unsigned cur = off;
#pragma unroll
    for (int k = 0; k < 8; ++k) {
        if (((m >> k) & 1u) && ((vm >> k) & 1u)) {
            unsigned rem = m >> (k + 1);
            int t1 = rem ? (lane * 8 + k + 1 + __ffs(rem) - 1) : cross_t1;
            int t0 = lane * 8 + k;
            s_run[warp][cur++] = vals[k] | ((unsigned)t0 << 9) | ((unsigned)t1 << 18);
        }
    }

    __syncthreads();

    // ---- Phase 2: gather own pixel. lanes = pg(bits 0-1) x r(bits 2-4) ----
    const int pg = lane & 3;
    const int r  = lane >> 2;                       // 0..7 run stride
    const int n  = s_n[warp];
    const float4* __restrict__ Ptab = (s_mode[warp] ? g_pc : g_pr) + pg;

    float4 acc = make_float4(0.f, 0.f, 0.f, 0.f);
    for (int j = r; j < n; j += 8) {
        unsigned word = s_run[warp][j];
        int ci = word & 511;
        int t0 = (word >> 9) & 511;
        int t1 = word >> 18;
        float4 lo = __ldg(Ptab + (ci * 257 + t0) * 4);
        float4 hi = __ldg(Ptab + (ci * 257 + t1) * 4);
        acc.x += hi.x - lo.x;
        acc.y += hi.y - lo.y;
        acc.z += hi.z - lo.z;
        acc.w += hi.w - lo.w;
    }

    // Butterfly-reduce over run-stride bits (2,3,4): all lanes get pg's full sum.
    acc.x += __shfl_xor_sync(FULLM, acc.x, 4);
    acc.y += __shfl_xor_sync(FULLM, acc.y, 4);
    acc.z += __shfl_xor_sync(FULLM, acc.z, 4);
    acc.w += __shfl_xor_sync(FULLM, acc.w, 4);
    acc.x += __shfl_xor_sync(FULLM, acc.x, 8);
    acc.y += __shfl_xor_sync(FULLM, acc.y, 8);
    acc.z += __shfl_xor_sync(FULLM, acc.z, 8);
    acc.w += __shfl_xor_sync(FULLM, acc.w, 8);
    acc.x += __shfl_xor_sync(FULLM, acc.x, 16);
    acc.y += __shfl_xor_sync(FULLM, acc.y, 16);
    acc.z += __shfl_xor_sync(FULLM, acc.z, 16);
    acc.w += __shfl_xor_sync(FULLM, acc.w, 16);

    // Lanes r=0..3 store one plane each: plane = pg*4 + r, component r of acc.
    if (r < 4) {
        float vout = (r == 0) ? acc.x : (r == 1) ? acc.y : (r == 2) ? acc.z : acc.w;
        out[(pg * 4 + r) * 65536 + px] = vout;
    }
}

extern "C" void kernel_launch(void* const* d_in, const int* in_sizes, int n_in,
                              void* d_out, int out_size) {
    const float* img = (const float*)d_in[0];
    const float* F   = (const float*)d_in[1];
    if (n_in >= 2 && in_sizes[0] == 9) {            // defensive: input order swap
        img = (const float*)d_in[1];
        F   = (const float*)d_in[0];
    }
    float* out = (float*)d_out;

    transpose_k<<<1024, 256>>>(img);
    prefix_k<<<256, 256>>>();
    fused_k<<<8192, 256>>>(F, out);
}